// round 2
// baseline (speedup 1.0000x reference)
#include <cuda_runtime.h>

#define NS 4096

// ---- scratch (device globals: no allocation allowed) ----
__device__ float g_P[512 * 256];     // prefix table  (c0,c1,c2)
__device__ float g_S[512 * 256];     // suffix table  (c5,c6,c7)
__device__ float g_V1[NS * 256];     // intermediate after level-3 GEMM
__device__ int   g_p[NS];            // prefix index per sample
__device__ int   g_q[NS];            // suffix index per sample
__device__ int   g_cnt3[8];
__device__ int   g_cnt4[8];
__device__ int   g_b3[8 * NS];       // bucket sample ids per level-3 digit
__device__ int   g_b4[8 * NS];       // bucket sample ids per level-4 digit

// ---------------------------------------------------------------------------
__global__ void k_zero() {
    if (threadIdx.x < 8) { g_cnt3[threadIdx.x] = 0; g_cnt4[threadIdx.x] = 0; }
}

// Decode coords -> digits, prefix/suffix indices, digit buckets for levels 3/4.
__global__ void k_decode(const int* __restrict__ coords) {
    int n = blockIdx.x * blockDim.x + threadIdx.x;
    if (n >= NS) return;
    int x = coords[3 * n], y = coords[3 * n + 1], z = coords[3 * n + 2];
    int d[8];
#pragma unroll
    for (int l = 0; l < 8; l++) {
        int sh = 7 - l;
        d[l] = 4 * ((x >> sh) & 1) + 2 * ((y >> sh) & 1) + ((z >> sh) & 1);
    }
    g_p[n] = d[0] * 64 + d[1] * 8 + d[2];
    g_q[n] = d[5] * 64 + d[6] * 8 + d[7];
    int pos3 = atomicAdd(&g_cnt3[d[3]], 1);
    g_b3[d[3] * NS + pos3] = n;
    int pos4 = atomicAdd(&g_cnt4[d[4]], 1);
    g_b4[d[4] * NS + pos4] = n;
}

// Prefix table: P[p] = core0[0,c0,:] @ core1[:,c1,:] @ core2[:,c2,:]
// core0: [1,8,8]  core1: [8,8,64]  core2: [64,8,256]
__global__ void k_prefix(const float* __restrict__ c0,
                         const float* __restrict__ c1,
                         const float* __restrict__ c2) {
    int pidx = blockIdx.x;
    int a = pidx >> 6, b = (pidx >> 3) & 7, c = pidx & 7;
    __shared__ float t[64];
    int tid = threadIdx.x;
    if (tid < 64) {
        float acc = 0.f;
#pragma unroll
        for (int i = 0; i < 8; i++)
            acc += c0[a * 8 + i] * c1[(i * 8 + b) * 64 + tid];
        t[tid] = acc;
    }
    __syncthreads();
    float acc = 0.f;
#pragma unroll 8
    for (int r = 0; r < 64; r++)
        acc += t[r] * c2[(r * 8 + c) * 256 + tid];
    g_P[pidx * 256 + tid] = acc;
}

// Suffix table: S[q] = core5[:,c5,:] @ (core6[:,c6,:] @ core7[:,c7,0])
// core5: [256,8,64]  core6: [64,8,8]  core7: [8,8,1]
__global__ void k_suffix(const float* __restrict__ c5,
                         const float* __restrict__ c6,
                         const float* __restrict__ c7) {
    int qidx = blockIdx.x;
    int a = qidx >> 6, b = (qidx >> 3) & 7, c = qidx & 7;  // c5,c6,c7 digits
    __shared__ float u[64];
    int tid = threadIdx.x;
    if (tid < 64) {
        float acc = 0.f;
#pragma unroll
        for (int i = 0; i < 8; i++)
            acc += c6[(tid * 8 + b) * 8 + i] * c7[i * 8 + c];
        u[tid] = acc;
    }
    __syncthreads();
    float acc = 0.f;
#pragma unroll 8
    for (int j = 0; j < 64; j++)
        acc += c5[(tid * 8 + a) * 64 + j] * u[j];
    g_S[qidx * 256 + tid] = acc;
}

// ---------------------------------------------------------------------------
// Level-3 GEMM: for samples in bucket c, V1[n,:] = P[p[n],:] @ core3[:,c,:]
// core3 element (k, c, s) at k*2048 + c*256 + s.
// Tile: 32 samples x 256 cols, K=256. 256 threads: tid&63 -> col/4, tid>>6 -> 8-sample group.
__global__ void k_gemm3(const float* __restrict__ B) {
    int c = blockIdx.y;
    int cnt = g_cnt3[c];
    int base = blockIdx.x * 32;
    if (base >= cnt) return;

    __shared__ float As[32][260];
    __shared__ int   sn[32];
    __shared__ int   sp[32];
    int tid = threadIdx.x;
    if (tid < 32) {
        int li = base + tid;
        int n = (li < cnt) ? g_b3[c * NS + li] : -1;
        sn[tid] = n;
        sp[tid] = (n >= 0) ? g_p[n] : 0;
    }
    __syncthreads();
    for (int idx = tid; idx < 32 * 64; idx += 256) {
        int row = idx >> 6, kc = idx & 63;
        float4 v = make_float4(0.f, 0.f, 0.f, 0.f);
        if (sn[row] >= 0)
            v = *(const float4*)(g_P + sp[row] * 256 + kc * 4);
        *(float4*)&As[row][kc * 4] = v;
    }
    __syncthreads();

    int colg = tid & 63;
    int sg = tid >> 6;
    const float* Bp = B + c * 256 + colg * 4;
    float acc[8][4];
#pragma unroll
    for (int i = 0; i < 8; i++) { acc[i][0] = 0.f; acc[i][1] = 0.f; acc[i][2] = 0.f; acc[i][3] = 0.f; }

    for (int k = 0; k < 256; k += 4) {
        float4 b0 = __ldg((const float4*)(Bp + (k + 0) * 2048));
        float4 b1 = __ldg((const float4*)(Bp + (k + 1) * 2048));
        float4 b2 = __ldg((const float4*)(Bp + (k + 2) * 2048));
        float4 b3 = __ldg((const float4*)(Bp + (k + 3) * 2048));
#pragma unroll
        for (int i = 0; i < 8; i++) {
            float4 a = *(const float4*)&As[sg * 8 + i][k];
            acc[i][0] += a.x * b0.x; acc[i][1] += a.x * b0.y; acc[i][2] += a.x * b0.z; acc[i][3] += a.x * b0.w;
            acc[i][0] += a.y * b1.x; acc[i][1] += a.y * b1.y; acc[i][2] += a.y * b1.z; acc[i][3] += a.y * b1.w;
            acc[i][0] += a.z * b2.x; acc[i][1] += a.z * b2.y; acc[i][2] += a.z * b2.z; acc[i][3] += a.z * b2.w;
            acc[i][0] += a.w * b3.x; acc[i][1] += a.w * b3.y; acc[i][2] += a.w * b3.z; acc[i][3] += a.w * b3.w;
        }
    }
#pragma unroll
    for (int i = 0; i < 8; i++) {
        int n = sn[sg * 8 + i];
        if (n >= 0) {
            float4 o = make_float4(acc[i][0], acc[i][1], acc[i][2], acc[i][3]);
            *(float4*)(g_V1 + n * 256 + colg * 4) = o;
        }
    }
}

// ---------------------------------------------------------------------------
// Level-4 GEMM + suffix dot: out[n] = (V1[n,:] @ core4[:,c,:]) . S[q[n],:]
__global__ void k_gemm4(const float* __restrict__ B, float* __restrict__ out) {
    int c = blockIdx.y;
    int cnt = g_cnt4[c];
    int base = blockIdx.x * 32;
    if (base >= cnt) return;

    __shared__ float As[32][260];
    __shared__ int   sn[32];
    __shared__ float wsum[8][8];
    int tid = threadIdx.x;
    if (tid < 32) {
        int li = base + tid;
        sn[tid] = (li < cnt) ? g_b4[c * NS + li] : -1;
    }
    __syncthreads();
    for (int idx = tid; idx < 32 * 64; idx += 256) {
        int row = idx >> 6, kc = idx & 63;
        int n = sn[row];
        float4 v = make_float4(0.f, 0.f, 0.f, 0.f);
        if (n >= 0)
            v = *(const float4*)(g_V1 + n * 256 + kc * 4);
        *(float4*)&As[row][kc * 4] = v;
    }
    __syncthreads();

    int colg = tid & 63;
    int sg = tid >> 6;
    const float* Bp = B + c * 256 + colg * 4;
    float acc[8][4];
#pragma unroll
    for (int i = 0; i < 8; i++) { acc[i][0] = 0.f; acc[i][1] = 0.f; acc[i][2] = 0.f; acc[i][3] = 0.f; }

    for (int k = 0; k < 256; k += 4) {
        float4 b0 = __ldg((const float4*)(Bp + (k + 0) * 2048));
        float4 b1 = __ldg((const float4*)(Bp + (k + 1) * 2048));
        float4 b2 = __ldg((const float4*)(Bp + (k + 2) * 2048));
        float4 b3 = __ldg((const float4*)(Bp + (k + 3) * 2048));
#pragma unroll
        for (int i = 0; i < 8; i++) {
            float4 a = *(const float4*)&As[sg * 8 + i][k];
            acc[i][0] += a.x * b0.x; acc[i][1] += a.x * b0.y; acc[i][2] += a.x * b0.z; acc[i][3] += a.x * b0.w;
            acc[i][0] += a.y * b1.x; acc[i][1] += a.y * b1.y; acc[i][2] += a.y * b1.z; acc[i][3] += a.y * b1.w;
            acc[i][0] += a.z * b2.x; acc[i][1] += a.z * b2.y; acc[i][2] += a.z * b2.z; acc[i][3] += a.z * b2.w;
            acc[i][0] += a.w * b3.x; acc[i][1] += a.w * b3.y; acc[i][2] += a.w * b3.z; acc[i][3] += a.w * b3.w;
        }
    }

    // dot each sample row with its suffix vector; deterministic reduction
    float part[8];
#pragma unroll
    for (int i = 0; i < 8; i++) {
        int n = sn[sg * 8 + i];
        int q = (n >= 0) ? g_q[n] : 0;
        float4 s4 = *(const float4*)(g_S + q * 256 + colg * 4);
        part[i] = acc[i][0] * s4.x + acc[i][1] * s4.y + acc[i][2] * s4.z + acc[i][3] * s4.w;
    }
#pragma unroll
    for (int i = 0; i < 8; i++) {
#pragma unroll
        for (int off = 16; off > 0; off >>= 1)
            part[i] += __shfl_xor_sync(0xffffffffu, part[i], off);
    }
    int warp = tid >> 5, lane = tid & 31;
    if (lane == 0) {
#pragma unroll
        for (int i = 0; i < 8; i++) wsum[warp][i] = part[i];
    }
    __syncthreads();
    if (tid < 32) {
        int sg2 = tid >> 3, i = tid & 7;
        int n = sn[sg2 * 8 + i];
        if (n >= 0) out[n] = wsum[2 * sg2][i] + wsum[2 * sg2 + 1][i];
    }
}

// ---------------------------------------------------------------------------
extern "C" void kernel_launch(void* const* d_in, const int* in_sizes, int n_in,
                              void* d_out, int out_size) {
    const float* core0 = (const float*)d_in[0];
    const float* core1 = (const float*)d_in[1];
    const float* core2 = (const float*)d_in[2];
    const float* core3 = (const float*)d_in[3];
    const float* core4 = (const float*)d_in[4];
    const float* core5 = (const float*)d_in[5];
    const float* core6 = (const float*)d_in[6];
    const float* core7 = (const float*)d_in[7];
    const int*   coords = (const int*)d_in[8];
    float* out = (float*)d_out;

    k_zero<<<1, 32>>>();
    k_decode<<<(NS + 255) / 256, 256>>>(coords);
    k_prefix<<<512, 256>>>(core0, core1, core2);
    k_suffix<<<512, 256>>>(core5, core6, core7);
    k_gemm3<<<dim3(128, 8), 256>>>(core3);
    k_gemm4<<<dim3(128, 8), 256>>>(core4, out);
}

// round 3
// speedup vs baseline: 1.4136x; 1.4136x over previous
#include <cuda_runtime.h>

#define NS 4096
typedef unsigned long long u64;

// f32x2 packed math (sm_103a): FFMA2 doubles fp32 FMA rate vs 3-reg FFMA (rt 1 vs 2 per lane-pair)
#define PACKDUP(d, x)  asm("mov.b64 %0, {%1, %1};" : "=l"(d) : "f"(x))
#define FFMA2(d, a, b) asm("fma.rn.f32x2 %0, %1, %2, %0;" : "+l"(d) : "l"(a), "l"(b))
#define UNPACK64(lo, hi, v) asm("mov.b64 {%0, %1}, %2;" : "=f"(lo), "=f"(hi) : "l"(v))

// ---- scratch (device globals: no allocation allowed) ----
__device__ float g_P[512 * 256];     // prefix table  (c0,c1,c2)
__device__ float g_S[512 * 256];     // suffix table  (c5,c6,c7)
__device__ float g_V1[NS * 256];     // intermediate after level-3 GEMM
__device__ int   g_p[NS];            // prefix index per sample
__device__ int   g_q[NS];            // suffix index per sample
__device__ int   g_cnt3[8];
__device__ int   g_cnt4[8];
__device__ int   g_b3[8 * NS];
__device__ int   g_b4[8 * NS];

// ---------------------------------------------------------------------------
__global__ void k_zero() {
    if (threadIdx.x < 8) { g_cnt3[threadIdx.x] = 0; g_cnt4[threadIdx.x] = 0; }
}

// ---------------------------------------------------------------------------
// Fused setup: blocks 0-31 prefix GEMMs, 32-63 suffix GEMMs, 64-79 decode.
// Prefix: for fixed c(=d2): P[(ab,c)][col] = T[ab][:64] @ core2[:, c, col]
//   T[ab][r] = sum_i core0[0,a,i]*core1[i,b,r]     (64x64)
// Suffix: for fixed a(=d5): S[(a,bc)][row] = core5[row,a,:64] @ U[bc][:64]
//   U[bc][j] = sum_i core6[j,b,i]*core7[i,c,0]     (64x64)
// Both are 64x64x64 GEMMs with 4x4 register tiles, conflict-free float4 LDS.
__global__ void __launch_bounds__(256) k_setup(
    const float* __restrict__ c0, const float* __restrict__ c1,
    const float* __restrict__ c2, const float* __restrict__ c5,
    const float* __restrict__ c6, const float* __restrict__ c7,
    const int*   __restrict__ coords)
{
    __shared__ float sA[64 * 68];
    __shared__ float sB[64 * 68];
    int bid = blockIdx.x;
    int tid = threadIdx.x;

    if (bid < 32) {
        // ---------------- prefix ----------------
        int cdig = bid >> 2, col0 = (bid & 3) * 64;
        // sA[r*68 + ab] = T[ab][r]
        for (int e = tid; e < 4096; e += 256) {
            int r = e >> 6, ab = e & 63;
            int a = ab >> 3, b = ab & 7;
            float acc = 0.f;
#pragma unroll
            for (int i = 0; i < 8; i++)
                acc += c0[a * 8 + i] * c1[(i * 8 + b) * 64 + r];
            sA[r * 68 + ab] = acc;
        }
        // sB[r*68 + cc] = core2[r, cdig, col0+cc]  (coalesced)
        for (int e = tid; e < 4096; e += 256) {
            int r = e >> 6, cc = e & 63;
            sB[r * 68 + cc] = c2[(r * 8 + cdig) * 256 + col0 + cc];
        }
        __syncthreads();
        int ct = tid & 15, abt = tid >> 4;
        float acc[4][4] = {};
        for (int r = 0; r < 64; r++) {
            float4 tv = *(const float4*)&sA[r * 68 + abt * 4];
            float4 bv = *(const float4*)&sB[r * 68 + ct * 4];
            acc[0][0] += tv.x * bv.x; acc[0][1] += tv.x * bv.y; acc[0][2] += tv.x * bv.z; acc[0][3] += tv.x * bv.w;
            acc[1][0] += tv.y * bv.x; acc[1][1] += tv.y * bv.y; acc[1][2] += tv.y * bv.z; acc[1][3] += tv.y * bv.w;
            acc[2][0] += tv.z * bv.x; acc[2][1] += tv.z * bv.y; acc[2][2] += tv.z * bv.z; acc[2][3] += tv.z * bv.w;
            acc[3][0] += tv.w * bv.x; acc[3][1] += tv.w * bv.y; acc[3][2] += tv.w * bv.z; acc[3][3] += tv.w * bv.w;
        }
#pragma unroll
        for (int ii = 0; ii < 4; ii++) {
            int p = (abt * 4 + ii) * 8 + cdig;
            *(float4*)&g_P[p * 256 + col0 + ct * 4] =
                make_float4(acc[ii][0], acc[ii][1], acc[ii][2], acc[ii][3]);
        }
    } else if (bid < 64) {
        // ---------------- suffix ----------------
        int b2 = bid - 32;
        int adig = b2 >> 2, row0 = (b2 & 3) * 64;
        // sA[j*68 + r] = core5[row0+r, adig, j]   (transposed; 4-way STS conflict, negligible)
        for (int e = tid; e < 4096; e += 256) {
            int r = e >> 6, j = e & 63;
            sA[j * 68 + r] = c5[((row0 + r) * 8 + adig) * 64 + j];
        }
        // sB[j*68 + bc] = U[bc][j]
        for (int e = tid; e < 4096; e += 256) {
            int j = e >> 6, bc = e & 63;
            int b = bc >> 3, c = bc & 7;
            float acc = 0.f;
#pragma unroll
            for (int i = 0; i < 8; i++)
                acc += c6[(j * 8 + b) * 8 + i] * c7[i * 8 + c];
            sB[j * 68 + bc] = acc;
        }
        __syncthreads();
        int rt = tid & 15, bct = tid >> 4;
        float acc[4][4] = {};
        for (int j = 0; j < 64; j++) {
            float4 av = *(const float4*)&sA[j * 68 + rt * 4];
            float4 uv = *(const float4*)&sB[j * 68 + bct * 4];
            acc[0][0] += av.x * uv.x; acc[0][1] += av.x * uv.y; acc[0][2] += av.x * uv.z; acc[0][3] += av.x * uv.w;
            acc[1][0] += av.y * uv.x; acc[1][1] += av.y * uv.y; acc[1][2] += av.y * uv.z; acc[1][3] += av.y * uv.w;
            acc[2][0] += av.z * uv.x; acc[2][1] += av.z * uv.y; acc[2][2] += av.z * uv.z; acc[2][3] += av.z * uv.w;
            acc[3][0] += av.w * uv.x; acc[3][1] += av.w * uv.y; acc[3][2] += av.w * uv.z; acc[3][3] += av.w * uv.w;
        }
#pragma unroll
        for (int jj = 0; jj < 4; jj++) {
            int q = adig * 64 + bct * 4 + jj;
            *(float4*)&g_S[q * 256 + row0 + rt * 4] =
                make_float4(acc[0][jj], acc[1][jj], acc[2][jj], acc[3][jj]);
        }
    } else {
        // ---------------- decode ----------------
        int n = (bid - 64) * 256 + tid;
        if (n < NS) {
            int x = coords[3 * n], y = coords[3 * n + 1], z = coords[3 * n + 2];
            int d[8];
#pragma unroll
            for (int l = 0; l < 8; l++) {
                int sh = 7 - l;
                d[l] = 4 * ((x >> sh) & 1) + 2 * ((y >> sh) & 1) + ((z >> sh) & 1);
            }
            g_p[n] = d[0] * 64 + d[1] * 8 + d[2];
            g_q[n] = d[5] * 64 + d[6] * 8 + d[7];
            int pos3 = atomicAdd(&g_cnt3[d[3]], 1);
            g_b3[d[3] * NS + pos3] = n;
            int pos4 = atomicAdd(&g_cnt4[d[4]], 1);
            g_b4[d[4] * NS + pos4] = n;
        }
    }
}

// ---------------------------------------------------------------------------
// FFMA2 GEMM core: 32 samples x 256 cols, K=256, 256 threads.
// A staged TRANSPOSED in smem (Ast[k][s], pad 36) so sample-pairs load as
// packed f32x2 via broadcast LDS. B streamed from L2 with 4-row register
// prefetch. acc[p][cc] = packed (sample 2p, 2p+1) for column colg*4+cc.
#define GEMM_BODY(AST, BPTR, ACC, COLG, SG)                                    \
    {                                                                          \
        float4 nb0 = __ldg((const float4*)(BPTR + 0 * 2048));                  \
        float4 nb1 = __ldg((const float4*)(BPTR + 1 * 2048));                  \
        float4 nb2 = __ldg((const float4*)(BPTR + 2 * 2048));                  \
        float4 nb3 = __ldg((const float4*)(BPTR + 3 * 2048));                  \
        for (int k = 0; k < 256; k += 4) {                                     \
            float4 cb[4] = {nb0, nb1, nb2, nb3};                               \
            int kp = (k + 4) & 255;                                            \
            nb0 = __ldg((const float4*)(BPTR + (kp + 0) * 2048));              \
            nb1 = __ldg((const float4*)(BPTR + (kp + 1) * 2048));              \
            nb2 = __ldg((const float4*)(BPTR + (kp + 2) * 2048));              \
            nb3 = __ldg((const float4*)(BPTR + (kp + 3) * 2048));              \
            _Pragma("unroll")                                                  \
            for (int kk = 0; kk < 4; kk++) {                                   \
                u64 bd0, bd1, bd2, bd3;                                        \
                PACKDUP(bd0, cb[kk].x); PACKDUP(bd1, cb[kk].y);                \
                PACKDUP(bd2, cb[kk].z); PACKDUP(bd3, cb[kk].w);                \
                const u64* ap = (const u64*)&AST[(k + kk) * 36 + SG * 8];      \
                u64 a0 = ap[0], a1 = ap[1], a2 = ap[2], a3 = ap[3];            \
                FFMA2(ACC[0][0], a0, bd0); FFMA2(ACC[0][1], a0, bd1);          \
                FFMA2(ACC[0][2], a0, bd2); FFMA2(ACC[0][3], a0, bd3);          \
                FFMA2(ACC[1][0], a1, bd0); FFMA2(ACC[1][1], a1, bd1);          \
                FFMA2(ACC[1][2], a1, bd2); FFMA2(ACC[1][3], a1, bd3);          \
                FFMA2(ACC[2][0], a2, bd0); FFMA2(ACC[2][1], a2, bd1);          \
                FFMA2(ACC[2][2], a2, bd2); FFMA2(ACC[2][3], a2, bd3);          \
                FFMA2(ACC[3][0], a3, bd0); FFMA2(ACC[3][1], a3, bd1);          \
                FFMA2(ACC[3][2], a3, bd2); FFMA2(ACC[3][3], a3, bd3);          \
            }                                                                  \
        }                                                                      \
    }

// Level-3: V1[n,:] = P[p[n],:] @ core3[:,c,:]
__global__ void __launch_bounds__(256) k_gemm3(const float* __restrict__ B) {
    int c = blockIdx.y;
    int cnt = g_cnt3[c];
    int base = blockIdx.x * 32;
    if (base >= cnt) return;

    __shared__ float Ast[256 * 36];
    __shared__ int   sn[32];
    __shared__ int   sp[32];
    int tid = threadIdx.x;
    if (tid < 32) {
        int li = base + tid;
        int n = (li < cnt) ? g_b3[c * NS + li] : -1;
        sn[tid] = n;
        sp[tid] = (n >= 0) ? g_p[n] : 0;
    }
    __syncthreads();
    // transpose-stage A: lanes = samples (conflict-free STS; scattered 16B LDG, MLP=8)
    for (int e = tid; e < 2048; e += 256) {
        int s = e & 31, kq = e >> 5;
        float4 v = make_float4(0.f, 0.f, 0.f, 0.f);
        if (sn[s] >= 0) v = *(const float4*)(g_P + sp[s] * 256 + kq * 4);
        Ast[(kq * 4 + 0) * 36 + s] = v.x;
        Ast[(kq * 4 + 1) * 36 + s] = v.y;
        Ast[(kq * 4 + 2) * 36 + s] = v.z;
        Ast[(kq * 4 + 3) * 36 + s] = v.w;
    }
    __syncthreads();

    int colg = tid & 63, sg = tid >> 6;
    const float* Bp = B + c * 256 + colg * 4;
    u64 acc[4][4] = {};
    GEMM_BODY(Ast, Bp, acc, colg, sg);

#pragma unroll
    for (int p = 0; p < 4; p++) {
        float lo0, lo1, lo2, lo3, hi0, hi1, hi2, hi3;
        UNPACK64(lo0, hi0, acc[p][0]); UNPACK64(lo1, hi1, acc[p][1]);
        UNPACK64(lo2, hi2, acc[p][2]); UNPACK64(lo3, hi3, acc[p][3]);
        int n0 = sn[sg * 8 + 2 * p], n1 = sn[sg * 8 + 2 * p + 1];
        if (n0 >= 0) *(float4*)&g_V1[n0 * 256 + colg * 4] = make_float4(lo0, lo1, lo2, lo3);
        if (n1 >= 0) *(float4*)&g_V1[n1 * 256 + colg * 4] = make_float4(hi0, hi1, hi2, hi3);
    }
}

// Level-4 + suffix dot: out[n] = (V1[n,:] @ core4[:,c,:]) . S[q[n],:]
__global__ void __launch_bounds__(256) k_gemm4(const float* __restrict__ B,
                                               float* __restrict__ out) {
    int c = blockIdx.y;
    int cnt = g_cnt4[c];
    int base = blockIdx.x * 32;
    if (base >= cnt) return;

    __shared__ float Ast[256 * 36];
    __shared__ int   sn[32];
    __shared__ int   sq[32];
    __shared__ float wsum[8][8];
    int tid = threadIdx.x;
    if (tid < 32) {
        int li = base + tid;
        int n = (li < cnt) ? g_b4[c * NS + li] : -1;
        sn[tid] = n;
        sq[tid] = (n >= 0) ? g_q[n] : 0;
    }
    __syncthreads();
    for (int e = tid; e < 2048; e += 256) {
        int s = e & 31, kq = e >> 5;
        float4 v = make_float4(0.f, 0.f, 0.f, 0.f);
        if (sn[s] >= 0) v = *(const float4*)(g_V1 + sn[s] * 256 + kq * 4);
        Ast[(kq * 4 + 0) * 36 + s] = v.x;
        Ast[(kq * 4 + 1) * 36 + s] = v.y;
        Ast[(kq * 4 + 2) * 36 + s] = v.z;
        Ast[(kq * 4 + 3) * 36 + s] = v.w;
    }
    __syncthreads();

    int colg = tid & 63, sg = tid >> 6;
    const float* Bp = B + c * 256 + colg * 4;
    u64 acc[4][4] = {};
    GEMM_BODY(Ast, Bp, acc, colg, sg);

    // per-sample dot with suffix vector (deterministic order)
    float part[8];
#pragma unroll
    for (int p = 0; p < 4; p++) {
        float lo0, lo1, lo2, lo3, hi0, hi1, hi2, hi3;
        UNPACK64(lo0, hi0, acc[p][0]); UNPACK64(lo1, hi1, acc[p][1]);
        UNPACK64(lo2, hi2, acc[p][2]); UNPACK64(lo3, hi3, acc[p][3]);
        int q0 = sq[sg * 8 + 2 * p], q1 = sq[sg * 8 + 2 * p + 1];
        float4 s0 = *(const float4*)(g_S + q0 * 256 + colg * 4);
        float4 s1 = *(const float4*)(g_S + q1 * 256 + colg * 4);
        part[2 * p]     = lo0 * s0.x + lo1 * s0.y + lo2 * s0.z + lo3 * s0.w;
        part[2 * p + 1] = hi0 * s1.x + hi1 * s1.y + hi2 * s1.z + hi3 * s1.w;
    }
#pragma unroll
    for (int i = 0; i < 8; i++) {
#pragma unroll
        for (int off = 16; off > 0; off >>= 1)
            part[i] += __shfl_xor_sync(0xffffffffu, part[i], off);
    }
    int warp = tid >> 5, lane = tid & 31;
    if (lane == 0) {
#pragma unroll
        for (int i = 0; i < 8; i++) wsum[warp][i] = part[i];
    }
    __syncthreads();
    if (tid < 32) {
        int sg2 = tid >> 3, i = tid & 7;
        int n = sn[sg2 * 8 + i];
        if (n >= 0) out[n] = wsum[2 * sg2][i] + wsum[2 * sg2 + 1][i];
    }
}

// ---------------------------------------------------------------------------
extern "C" void kernel_launch(void* const* d_in, const int* in_sizes, int n_in,
                              void* d_out, int out_size) {
    const float* core0 = (const float*)d_in[0];
    const float* core1 = (const float*)d_in[1];
    const float* core2 = (const float*)d_in[2];
    const float* core3 = (const float*)d_in[3];
    const float* core4 = (const float*)d_in[4];
    const float* core5 = (const float*)d_in[5];
    const float* core6 = (const float*)d_in[6];
    const float* core7 = (const float*)d_in[7];
    const int*   coords = (const int*)d_in[8];
    float* out = (float*)d_out;

    k_zero<<<1, 32>>>();
    k_setup<<<80, 256>>>(core0, core1, core2, core5, core6, core7, coords);
    k_gemm3<<<dim3(128, 8), 256>>>(core3);
    k_gemm4<<<dim3(128, 8), 256>>>(core4, out);
}

// round 4
// speedup vs baseline: 2.2155x; 1.5673x over previous
#include <cuda_runtime.h>

#define NS 4096
typedef unsigned long long u64;

// f32x2 packed math (sm_103a): one FFMA2 = 2 fp32 FMAs
#define PACKDUP(d, x)  asm("mov.b64 %0, {%1, %1};" : "=l"(d) : "f"(x))
#define FFMA2(d, a, b) asm("fma.rn.f32x2 %0, %1, %2, %0;" : "+l"(d) : "l"(a), "l"(b))
#define UNPACK64(lo, hi, v) asm("mov.b64 {%0, %1}, %2;" : "=f"(lo), "=f"(hi) : "l"(v))

// ---- scratch (device globals: no allocation allowed) ----
__device__ float g_P[512 * 256];     // prefix table  (c0,c1,c2)
__device__ float g_S[512 * 256];     // suffix table  (c5,c6,c7)
__device__ float g_V1[NS * 256];     // intermediate after level-3 GEMM
__device__ float g_part[2 * NS];     // per-col-half partial dots (level 4)
__device__ int   g_p[NS];
__device__ int   g_q[NS];
__device__ int   g_cnt3[8];
__device__ int   g_cnt4[8];
__device__ int   g_b3[8 * NS];
__device__ int   g_b4[8 * NS];

// ---------------------------------------------------------------------------
__global__ void k_zero() {
    if (threadIdx.x < 8) { g_cnt3[threadIdx.x] = 0; g_cnt4[threadIdx.x] = 0; }
}

// ---------------------------------------------------------------------------
// Fused setup: blocks 0-31 prefix GEMMs, 32-63 suffix GEMMs, 64-79 decode.
__global__ void __launch_bounds__(256) k_setup(
    const float* __restrict__ c0, const float* __restrict__ c1,
    const float* __restrict__ c2, const float* __restrict__ c5,
    const float* __restrict__ c6, const float* __restrict__ c7,
    const int*   __restrict__ coords)
{
    __shared__ float sA[64 * 68];
    __shared__ float sB[64 * 68];
    int bid = blockIdx.x;
    int tid = threadIdx.x;

    if (bid < 32) {
        // ---------------- prefix: P[(ab,c)][col] = T[ab] @ core2[:,c,col] ----
        int cdig = bid >> 2, col0 = (bid & 3) * 64;
        for (int e = tid; e < 4096; e += 256) {
            int r = e >> 6, ab = e & 63;
            int a = ab >> 3, b = ab & 7;
            float acc = 0.f;
#pragma unroll
            for (int i = 0; i < 8; i++)
                acc += c0[a * 8 + i] * c1[(i * 8 + b) * 64 + r];
            sA[r * 68 + ab] = acc;
        }
        for (int e = tid; e < 4096; e += 256) {
            int r = e >> 6, cc = e & 63;
            sB[r * 68 + cc] = c2[(r * 8 + cdig) * 256 + col0 + cc];
        }
        __syncthreads();
        int ct = tid & 15, abt = tid >> 4;
        float acc[4][4] = {};
        for (int r = 0; r < 64; r++) {
            float4 tv = *(const float4*)&sA[r * 68 + abt * 4];
            float4 bv = *(const float4*)&sB[r * 68 + ct * 4];
            acc[0][0] += tv.x * bv.x; acc[0][1] += tv.x * bv.y; acc[0][2] += tv.x * bv.z; acc[0][3] += tv.x * bv.w;
            acc[1][0] += tv.y * bv.x; acc[1][1] += tv.y * bv.y; acc[1][2] += tv.y * bv.z; acc[1][3] += tv.y * bv.w;
            acc[2][0] += tv.z * bv.x; acc[2][1] += tv.z * bv.y; acc[2][2] += tv.z * bv.z; acc[2][3] += tv.z * bv.w;
            acc[3][0] += tv.w * bv.x; acc[3][1] += tv.w * bv.y; acc[3][2] += tv.w * bv.z; acc[3][3] += tv.w * bv.w;
        }
#pragma unroll
        for (int ii = 0; ii < 4; ii++) {
            int p = (abt * 4 + ii) * 8 + cdig;
            *(float4*)&g_P[p * 256 + col0 + ct * 4] =
                make_float4(acc[ii][0], acc[ii][1], acc[ii][2], acc[ii][3]);
        }
    } else if (bid < 64) {
        // ---------------- suffix: S[(a,bc)][row] = core5[row,a,:] @ U[bc] ----
        int b2 = bid - 32;
        int adig = b2 >> 2, row0 = (b2 & 3) * 64;
        for (int e = tid; e < 4096; e += 256) {
            int r = e >> 6, j = e & 63;
            sA[j * 68 + r] = c5[((row0 + r) * 8 + adig) * 64 + j];
        }
        for (int e = tid; e < 4096; e += 256) {
            int j = e >> 6, bc = e & 63;
            int b = bc >> 3, c = bc & 7;
            float acc = 0.f;
#pragma unroll
            for (int i = 0; i < 8; i++)
                acc += c6[(j * 8 + b) * 8 + i] * c7[i * 8 + c];
            sB[j * 68 + bc] = acc;
        }
        __syncthreads();
        int rt = tid & 15, bct = tid >> 4;
        float acc[4][4] = {};
        for (int j = 0; j < 64; j++) {
            float4 av = *(const float4*)&sA[j * 68 + rt * 4];
            float4 uv = *(const float4*)&sB[j * 68 + bct * 4];
            acc[0][0] += av.x * uv.x; acc[0][1] += av.x * uv.y; acc[0][2] += av.x * uv.z; acc[0][3] += av.x * uv.w;
            acc[1][0] += av.y * uv.x; acc[1][1] += av.y * uv.y; acc[1][2] += av.y * uv.z; acc[1][3] += av.y * uv.w;
            acc[2][0] += av.z * uv.x; acc[2][1] += av.z * uv.y; acc[2][2] += av.z * uv.z; acc[2][3] += av.z * uv.w;
            acc[3][0] += av.w * uv.x; acc[3][1] += av.w * uv.y; acc[3][2] += av.w * uv.z; acc[3][3] += av.w * uv.w;
        }
#pragma unroll
        for (int jj = 0; jj < 4; jj++) {
            int q = adig * 64 + bct * 4 + jj;
            *(float4*)&g_S[q * 256 + row0 + rt * 4] =
                make_float4(acc[0][jj], acc[1][jj], acc[2][jj], acc[3][jj]);
        }
    } else {
        // ---------------- decode ----------------
        int n = (bid - 64) * 256 + tid;
        if (n < NS) {
            int x = coords[3 * n], y = coords[3 * n + 1], z = coords[3 * n + 2];
            int d[8];
#pragma unroll
            for (int l = 0; l < 8; l++) {
                int sh = 7 - l;
                d[l] = 4 * ((x >> sh) & 1) + 2 * ((y >> sh) & 1) + ((z >> sh) & 1);
            }
            g_p[n] = d[0] * 64 + d[1] * 8 + d[2];
            g_q[n] = d[5] * 64 + d[6] * 8 + d[7];
            int pos3 = atomicAdd(&g_cnt3[d[3]], 1);
            g_b3[d[3] * NS + pos3] = n;
            int pos4 = atomicAdd(&g_cnt4[d[4]], 1);
            g_b4[d[4] * NS + pos4] = n;
        }
    }
}

// ---------------------------------------------------------------------------
// FFMA2 GEMM core: 32 samples x 128 cols (col half = blockIdx.y), K=256.
// 256 threads: colg = tid&31 (4 cols each), sg = tid>>5 (4 samples each = 2 pairs).
// A staged transposed in smem; B streamed from L2 with 4-row register prefetch.
#define GEMM_INNER(AST, BPTR, ACC, SG4)                                        \
    {                                                                          \
        float4 nb0 = __ldg((const float4*)(BPTR + 0 * 2048));                  \
        float4 nb1 = __ldg((const float4*)(BPTR + 1 * 2048));                  \
        float4 nb2 = __ldg((const float4*)(BPTR + 2 * 2048));                  \
        float4 nb3 = __ldg((const float4*)(BPTR + 3 * 2048));                  \
        for (int k = 0; k < 256; k += 4) {                                     \
            float4 cb[4] = {nb0, nb1, nb2, nb3};                               \
            int kp = (k + 4) & 255;                                            \
            nb0 = __ldg((const float4*)(BPTR + (kp + 0) * 2048));              \
            nb1 = __ldg((const float4*)(BPTR + (kp + 1) * 2048));              \
            nb2 = __ldg((const float4*)(BPTR + (kp + 2) * 2048));              \
            nb3 = __ldg((const float4*)(BPTR + (kp + 3) * 2048));              \
            _Pragma("unroll")                                                  \
            for (int kk = 0; kk < 4; kk++) {                                   \
                u64 bd0, bd1, bd2, bd3;                                        \
                PACKDUP(bd0, cb[kk].x); PACKDUP(bd1, cb[kk].y);                \
                PACKDUP(bd2, cb[kk].z); PACKDUP(bd3, cb[kk].w);                \
                const u64* ap = (const u64*)&AST[(k + kk) * 36 + SG4];         \
                u64 a0 = ap[0], a1 = ap[1];                                    \
                FFMA2(ACC[0][0], a0, bd0); FFMA2(ACC[0][1], a0, bd1);          \
                FFMA2(ACC[0][2], a0, bd2); FFMA2(ACC[0][3], a0, bd3);          \
                FFMA2(ACC[1][0], a1, bd0); FFMA2(ACC[1][1], a1, bd1);          \
                FFMA2(ACC[1][2], a1, bd2); FFMA2(ACC[1][3], a1, bd3);          \
            }                                                                  \
        }                                                                      \
    }

// Map flat tile id -> (bucket c, sample base) via prefix sum of ceil(cnt/32).
__device__ __forceinline__ void tile_map(const int* __restrict__ cnt, int t,
                                         int* c_out, int* base_out) {
    int acc = 0, c = -1, base = 0;
#pragma unroll
    for (int i = 0; i < 8; i++) {
        int tiles = (cnt[i] + 31) >> 5;
        if (c < 0 && t < acc + tiles) { c = i; base = (t - acc) * 32; }
        acc += tiles;
    }
    *c_out = c; *base_out = base;
}

// Level-3: V1[n, half] = P[p[n],:] @ core3[:,c, half-cols]
__global__ void __launch_bounds__(256) k_gemm3(const float* __restrict__ B) {
    __shared__ float Ast[256 * 36];
    __shared__ int   sn[32];
    __shared__ int   sp[32];
    __shared__ int   s_c, s_base;
    int tid = threadIdx.x;
    if (tid == 0) tile_map(g_cnt3, blockIdx.x, (int*)&s_c, (int*)&s_base);
    __syncthreads();
    int c = s_c;
    if (c < 0) return;
    int base = s_base, cnt = g_cnt3[c];

    if (tid < 32) {
        int li = base + tid;
        int n = (li < cnt) ? g_b3[c * NS + li] : -1;
        sn[tid] = n;
        sp[tid] = (n >= 0) ? g_p[n] : 0;
    }
    __syncthreads();
    for (int e = tid; e < 2048; e += 256) {
        int s = e & 31, kq = e >> 5;
        float4 v = make_float4(0.f, 0.f, 0.f, 0.f);
        if (sn[s] >= 0) v = *(const float4*)(g_P + sp[s] * 256 + kq * 4);
        Ast[(kq * 4 + 0) * 36 + s] = v.x;
        Ast[(kq * 4 + 1) * 36 + s] = v.y;
        Ast[(kq * 4 + 2) * 36 + s] = v.z;
        Ast[(kq * 4 + 3) * 36 + s] = v.w;
    }
    __syncthreads();

    int half = blockIdx.y;
    int colg = tid & 31, sg = tid >> 5;
    const float* Bp = B + c * 256 + half * 128 + colg * 4;
    u64 acc[2][4] = {};
    GEMM_INNER(Ast, Bp, acc, sg * 4);

#pragma unroll
    for (int p = 0; p < 2; p++) {
        float lo0, lo1, lo2, lo3, hi0, hi1, hi2, hi3;
        UNPACK64(lo0, hi0, acc[p][0]); UNPACK64(lo1, hi1, acc[p][1]);
        UNPACK64(lo2, hi2, acc[p][2]); UNPACK64(lo3, hi3, acc[p][3]);
        int n0 = sn[sg * 4 + 2 * p], n1 = sn[sg * 4 + 2 * p + 1];
        if (n0 >= 0) *(float4*)&g_V1[n0 * 256 + half * 128 + colg * 4] =
            make_float4(lo0, lo1, lo2, lo3);
        if (n1 >= 0) *(float4*)&g_V1[n1 * 256 + half * 128 + colg * 4] =
            make_float4(hi0, hi1, hi2, hi3);
    }
}

// Level-4 + suffix dot (per col half): g_part[half][n] = (V1[n]@C4[c])[half] . S[q[n]][half]
__global__ void __launch_bounds__(256) k_gemm4(const float* __restrict__ B) {
    __shared__ float Ast[256 * 36];
    __shared__ int   sn[32];
    __shared__ int   sq[32];
    __shared__ int   s_c, s_base;
    int tid = threadIdx.x;
    if (tid == 0) tile_map(g_cnt4, blockIdx.x, (int*)&s_c, (int*)&s_base);
    __syncthreads();
    int c = s_c;
    if (c < 0) return;
    int base = s_base, cnt = g_cnt4[c];

    if (tid < 32) {
        int li = base + tid;
        int n = (li < cnt) ? g_b4[c * NS + li] : -1;
        sn[tid] = n;
        sq[tid] = (n >= 0) ? g_q[n] : 0;
    }
    __syncthreads();
    for (int e = tid; e < 2048; e += 256) {
        int s = e & 31, kq = e >> 5;
        float4 v = make_float4(0.f, 0.f, 0.f, 0.f);
        if (sn[s] >= 0) v = *(const float4*)(g_V1 + sn[s] * 256 + kq * 4);
        Ast[(kq * 4 + 0) * 36 + s] = v.x;
        Ast[(kq * 4 + 1) * 36 + s] = v.y;
        Ast[(kq * 4 + 2) * 36 + s] = v.z;
        Ast[(kq * 4 + 3) * 36 + s] = v.w;
    }
    __syncthreads();

    int half = blockIdx.y;
    int colg = tid & 31, sg = tid >> 5;
    const float* Bp = B + c * 256 + half * 128 + colg * 4;
    u64 acc[2][4] = {};
    GEMM_INNER(Ast, Bp, acc, sg * 4);

    // dot each sample's 4 cols with suffix vector, then butterfly over the
    // warp (32 lanes = all 32 col-groups of this half) -> full half-dot.
    float part[4];
#pragma unroll
    for (int p = 0; p < 2; p++) {
        float lo0, lo1, lo2, lo3, hi0, hi1, hi2, hi3;
        UNPACK64(lo0, hi0, acc[p][0]); UNPACK64(lo1, hi1, acc[p][1]);
        UNPACK64(lo2, hi2, acc[p][2]); UNPACK64(lo3, hi3, acc[p][3]);
        int q0 = sq[sg * 4 + 2 * p], q1 = sq[sg * 4 + 2 * p + 1];
        float4 s0 = *(const float4*)(g_S + q0 * 256 + half * 128 + colg * 4);
        float4 s1 = *(const float4*)(g_S + q1 * 256 + half * 128 + colg * 4);
        part[2 * p]     = lo0 * s0.x + lo1 * s0.y + lo2 * s0.z + lo3 * s0.w;
        part[2 * p + 1] = hi0 * s1.x + hi1 * s1.y + hi2 * s1.z + hi3 * s1.w;
    }
#pragma unroll
    for (int i = 0; i < 4; i++) {
#pragma unroll
        for (int off = 16; off > 0; off >>= 1)
            part[i] += __shfl_xor_sync(0xffffffffu, part[i], off);
    }
    if (colg == 0) {
#pragma unroll
        for (int i = 0; i < 4; i++) {
            int n = sn[sg * 4 + i];
            if (n >= 0) g_part[half * NS + n] = part[i];
        }
    }
}

// Sum the two column-half partials -> final output.
__global__ void k_final(float* __restrict__ out) {
    int n = blockIdx.x * 256 + threadIdx.x;
    if (n < NS) out[n] = g_part[n] + g_part[NS + n];
}

// ---------------------------------------------------------------------------
extern "C" void kernel_launch(void* const* d_in, const int* in_sizes, int n_in,
                              void* d_out, int out_size) {
    const float* core0 = (const float*)d_in[0];
    const float* core1 = (const float*)d_in[1];
    const float* core2 = (const float*)d_in[2];
    const float* core3 = (const float*)d_in[3];
    const float* core4 = (const float*)d_in[4];
    const float* core5 = (const float*)d_in[5];
    const float* core6 = (const float*)d_in[6];
    const float* core7 = (const float*)d_in[7];
    const int*   coords = (const int*)d_in[8];
    float* out = (float*)d_out;

    k_zero<<<1, 32>>>();
    k_setup<<<80, 256>>>(core0, core1, core2, core5, core6, core7, coords);
    k_gemm3<<<dim3(136, 2), 256>>>(core3);
    k_gemm4<<<dim3(136, 2), 256>>>(core4);
    k_final<<<16, 256>>>(out);
}

// round 7
// speedup vs baseline: 2.2238x; 1.0037x over previous
#include <cuda_runtime.h>

#define NS 4096
typedef unsigned long long u64;

// f32x2 packed math (sm_103a): one FFMA2 = 2 fp32 FMAs
#define PACKDUP(d, x)  asm("mov.b64 %0, {%1, %1};" : "=l"(d) : "f"(x))
#define FFMA2(d, a, b) asm("fma.rn.f32x2 %0, %1, %2, %0;" : "+l"(d) : "l"(a), "l"(b))
#define UNPACK64(lo, hi, v) asm("mov.b64 {%0, %1}, %2;" : "=f"(lo), "=f"(hi) : "l"(v))

// ---- scratch (device globals: no allocation allowed) ----
__device__ float g_P[512 * 256];     // prefix table  (c0,c1,c2)
__device__ float g_S[512 * 256];     // suffix table  (c5,c6,c7)
__device__ float g_V1[NS * 256];     // intermediate after level-3 GEMM
__device__ float g_part[2 * NS];     // per-col-half partial dots (level 4)
__device__ int   g_p[NS];
__device__ int   g_q[NS];
__device__ int   g_cnt3[8];
__device__ int   g_cnt4[8];
__device__ int   g_b3[8 * NS];
__device__ int   g_b4[8 * NS];

// ---------------------------------------------------------------------------
__global__ void k_zero() {
    if (threadIdx.x < 8) { g_cnt3[threadIdx.x] = 0; g_cnt4[threadIdx.x] = 0; }
}

// ---------------------------------------------------------------------------
// Fused setup: blocks 0-31 prefix GEMMs, 32-63 suffix GEMMs, 64-79 decode.
__global__ void __launch_bounds__(256) k_setup(
    const float* __restrict__ c0, const float* __restrict__ c1,
    const float* __restrict__ c2, const float* __restrict__ c5,
    const float* __restrict__ c6, const float* __restrict__ c7,
    const int*   __restrict__ coords)
{
    __shared__ float sA[64 * 68];
    __shared__ float sB[64 * 68];
    int bid = blockIdx.x;
    int tid = threadIdx.x;

    if (bid < 32) {
        // ---------------- prefix: P[(ab,c)][col] = T[ab] @ core2[:,c,col] ----
        int cdig = bid >> 2, col0 = (bid & 3) * 64;
        for (int e = tid; e < 4096; e += 256) {
            int r = e >> 6, ab = e & 63;
            int a = ab >> 3, b = ab & 7;
            float acc = 0.f;
#pragma unroll
            for (int i = 0; i < 8; i++)
                acc += c0[a * 8 + i] * c1[(i * 8 + b) * 64 + r];
            sA[r * 68 + ab] = acc;
        }
        for (int e = tid; e < 4096; e += 256) {
            int r = e >> 6, cc = e & 63;
            sB[r * 68 + cc] = c2[(r * 8 + cdig) * 256 + col0 + cc];
        }
        __syncthreads();
        int ct = tid & 15, abt = tid >> 4;
        float acc[4][4] = {};
        for (int r = 0; r < 64; r++) {
            float4 tv = *(const float4*)&sA[r * 68 + abt * 4];
            float4 bv = *(const float4*)&sB[r * 68 + ct * 4];
            acc[0][0] += tv.x * bv.x; acc[0][1] += tv.x * bv.y; acc[0][2] += tv.x * bv.z; acc[0][3] += tv.x * bv.w;
            acc[1][0] += tv.y * bv.x; acc[1][1] += tv.y * bv.y; acc[1][2] += tv.y * bv.z; acc[1][3] += tv.y * bv.w;
            acc[2][0] += tv.z * bv.x; acc[2][1] += tv.z * bv.y; acc[2][2] += tv.z * bv.z; acc[2][3] += tv.z * bv.w;
            acc[3][0] += tv.w * bv.x; acc[3][1] += tv.w * bv.y; acc[3][2] += tv.w * bv.z; acc[3][3] += tv.w * bv.w;
        }
#pragma unroll
        for (int ii = 0; ii < 4; ii++) {
            int p = (abt * 4 + ii) * 8 + cdig;
            *(float4*)&g_P[p * 256 + col0 + ct * 4] =
                make_float4(acc[ii][0], acc[ii][1], acc[ii][2], acc[ii][3]);
        }
    } else if (bid < 64) {
        // ---------------- suffix: S[(a,bc)][row] = core5[row,a,:] @ U[bc] ----
        int b2 = bid - 32;
        int adig = b2 >> 2, row0 = (b2 & 3) * 64;
        for (int e = tid; e < 4096; e += 256) {
            int r = e >> 6, j = e & 63;
            sA[j * 68 + r] = c5[((row0 + r) * 8 + adig) * 64 + j];
        }
        for (int e = tid; e < 4096; e += 256) {
            int j = e >> 6, bc = e & 63;
            int b = bc >> 3, c = bc & 7;
            float acc = 0.f;
#pragma unroll
            for (int i = 0; i < 8; i++)
                acc += c6[(j * 8 + b) * 8 + i] * c7[i * 8 + c];
            sB[j * 68 + bc] = acc;
        }
        __syncthreads();
        int rt = tid & 15, bct = tid >> 4;
        float acc[4][4] = {};
        for (int j = 0; j < 64; j++) {
            float4 av = *(const float4*)&sA[j * 68 + rt * 4];
            float4 uv = *(const float4*)&sB[j * 68 + bct * 4];
            acc[0][0] += av.x * uv.x; acc[0][1] += av.x * uv.y; acc[0][2] += av.x * uv.z; acc[0][3] += av.x * uv.w;
            acc[1][0] += av.y * uv.x; acc[1][1] += av.y * uv.y; acc[1][2] += av.y * uv.z; acc[1][3] += av.y * uv.w;
            acc[2][0] += av.z * uv.x; acc[2][1] += av.z * uv.y; acc[2][2] += av.z * uv.z; acc[2][3] += av.z * uv.w;
            acc[3][0] += av.w * uv.x; acc[3][1] += av.w * uv.y; acc[3][2] += av.w * uv.z; acc[3][3] += av.w * uv.w;
        }
#pragma unroll
        for (int jj = 0; jj < 4; jj++) {
            int q = adig * 64 + bct * 4 + jj;
            *(float4*)&g_S[q * 256 + row0 + rt * 4] =
                make_float4(acc[0][jj], acc[1][jj], acc[2][jj], acc[3][jj]);
        }
    } else {
        // ---------------- decode ----------------
        int n = (bid - 64) * 256 + tid;
        if (n < NS) {
            int x = coords[3 * n], y = coords[3 * n + 1], z = coords[3 * n + 2];
            int d[8];
#pragma unroll
            for (int l = 0; l < 8; l++) {
                int sh = 7 - l;
                d[l] = 4 * ((x >> sh) & 1) + 2 * ((y >> sh) & 1) + ((z >> sh) & 1);
            }
            g_p[n] = d[0] * 64 + d[1] * 8 + d[2];
            g_q[n] = d[5] * 64 + d[6] * 8 + d[7];
            int pos3 = atomicAdd(&g_cnt3[d[3]], 1);
            g_b3[d[3] * NS + pos3] = n;
            int pos4 = atomicAdd(&g_cnt4[d[4]], 1);
            g_b4[d[4] * NS + pos4] = n;
        }
    }
}

// ---------------------------------------------------------------------------
// Pipelined FFMA2 GEMM: 32 samples x 128 cols (half = blockIdx.y), K=256.
// K processed in 8 chunks of 32. Chunk kc+1 streams gmem->regs while chunk kc
// computes purely from smem; regs->smem at chunk boundary. 256 threads:
// colg=tid&31 (4 cols), sg=tid>>5 (4 samples = 2 packed pairs).
// Shared: Ast[256][32] transposed A (32KB) + Bs[32][128] (16KB) = 48KB exact.

// map flat tile id -> (bucket, base); computed redundantly in all threads
__device__ __forceinline__ int2 tile_map(const int* __restrict__ cnt, int t) {
    int acc = 0, c = -1, base = 0;
#pragma unroll
    for (int i = 0; i < 8; i++) {
        int tiles = (cnt[i] + 31) >> 5;
        if (c < 0 && t < acc + tiles) { c = i; base = (t - acc) * 32; }
        acc += tiles;
    }
    return make_int2(c, base);
}

#define LDB(KC)                                                                \
    {                                                                          \
        _Pragma("unroll")                                                      \
        for (int p4 = 0; p4 < 4; p4++)                                         \
            nb[p4] = __ldg((const float4*)(Bg + ((KC) * 32 + p4 * 8 + brow) * 2048 + bcol)); \
    }
#define STB()                                                                  \
    {                                                                          \
        _Pragma("unroll")                                                      \
        for (int p4 = 0; p4 < 4; p4++)                                         \
            *(float4*)&Bs[(p4 * 8 + brow) * 128 + bcol] = nb[p4];              \
    }
#define CHUNK_COMPUTE(KC)                                                      \
    {                                                                          \
        _Pragma("unroll 8")                                                    \
        for (int kk = 0; kk < 32; kk++) {                                      \
            float4 b = *(const float4*)&Bs[kk * 128 + colg * 4];               \
            u64 bd0, bd1, bd2, bd3;                                            \
            PACKDUP(bd0, b.x); PACKDUP(bd1, b.y);                              \
            PACKDUP(bd2, b.z); PACKDUP(bd3, b.w);                              \
            const u64* ap = (const u64*)&Ast[((KC) * 32 + kk) * 32 + sg * 4];  \
            u64 a0 = ap[0], a1 = ap[1];                                        \
            FFMA2(acc[0][0], a0, bd0); FFMA2(acc[0][1], a0, bd1);              \
            FFMA2(acc[0][2], a0, bd2); FFMA2(acc[0][3], a0, bd3);              \
            FFMA2(acc[1][0], a1, bd0); FFMA2(acc[1][1], a1, bd1);              \
            FFMA2(acc[1][2], a1, bd2); FFMA2(acc[1][3], a1, bd3);              \
        }                                                                      \
    }
#define GEMM_MAIN()                                                            \
    LDB(0); STB(); __syncthreads();                                            \
    for (int kc = 0; kc < 8; kc++) {                                           \
        if (kc < 7) LDB(kc + 1);                                               \
        CHUNK_COMPUTE(kc);                                                     \
        __syncthreads();                                                       \
        if (kc < 7) { STB(); __syncthreads(); }                                \
    }

// Level-3: V1[n, half] = P[p[n],:] @ core3[:,c, half-cols]
__global__ void __launch_bounds__(256) k_gemm3(const float* __restrict__ B) {
    __shared__ float Ast[256 * 32];
    __shared__ float Bs[32 * 128];
    int tid = threadIdx.x;
    int2 cb = tile_map(g_cnt3, blockIdx.x);
    int c = cb.x;
    if (c < 0) return;
    int base = cb.y, cnt = g_cnt3[c];

    // stage A transposed: thread owns sample s = tid&31 across all passes
    int s = tid & 31;
    int li = base + s;
    int n_own = (li < cnt) ? g_b3[c * NS + li] : -1;
    int prow = (n_own >= 0) ? g_p[n_own] : 0;
#pragma unroll
    for (int pass = 0; pass < 8; pass++) {
        int kq = (tid >> 5) + 8 * pass;
        float4 v = make_float4(0.f, 0.f, 0.f, 0.f);
        if (n_own >= 0) v = __ldg((const float4*)(g_P + prow * 256 + kq * 4));
        Ast[(kq * 4 + 0) * 32 + s] = v.x;
        Ast[(kq * 4 + 1) * 32 + s] = v.y;
        Ast[(kq * 4 + 2) * 32 + s] = v.z;
        Ast[(kq * 4 + 3) * 32 + s] = v.w;
    }
    __syncthreads();

    int half = blockIdx.y;
    int colg = tid & 31, sg = tid >> 5;
    int brow = tid >> 5, bcol = (tid & 31) * 4;
    const float* Bg = B + c * 256 + half * 128;
    float4 nb[4];
    u64 acc[2][4] = {};
    GEMM_MAIN();

    // epilogue: sample ids for this thread's 4 samples
#pragma unroll
    for (int p = 0; p < 2; p++) {
        float lo0, lo1, lo2, lo3, hi0, hi1, hi2, hi3;
        UNPACK64(lo0, hi0, acc[p][0]); UNPACK64(lo1, hi1, acc[p][1]);
        UNPACK64(lo2, hi2, acc[p][2]); UNPACK64(lo3, hi3, acc[p][3]);
        int l0 = base + sg * 4 + 2 * p, l1 = l0 + 1;
        int n0 = (l0 < cnt) ? g_b3[c * NS + l0] : -1;
        int n1 = (l1 < cnt) ? g_b3[c * NS + l1] : -1;
        if (n0 >= 0) *(float4*)&g_V1[n0 * 256 + half * 128 + colg * 4] =
            make_float4(lo0, lo1, lo2, lo3);
        if (n1 >= 0) *(float4*)&g_V1[n1 * 256 + half * 128 + colg * 4] =
            make_float4(hi0, hi1, hi2, hi3);
    }
}

// Level-4 + suffix dot: g_part[half][n] = (V1[n]@C4[c])[half] . S[q[n]][half]
__global__ void __launch_bounds__(256) k_gemm4(const float* __restrict__ B) {
    __shared__ float Ast[256 * 32];
    __shared__ float Bs[32 * 128];
    int tid = threadIdx.x;
    int2 cb = tile_map(g_cnt4, blockIdx.x);
    int c = cb.x;
    if (c < 0) return;
    int base = cb.y, cnt = g_cnt4[c];

    int s = tid & 31;
    int li = base + s;
    int n_own = (li < cnt) ? g_b4[c * NS + li] : -1;
#pragma unroll
    for (int pass = 0; pass < 8; pass++) {
        int kq = (tid >> 5) + 8 * pass;
        float4 v = make_float4(0.f, 0.f, 0.f, 0.f);
        if (n_own >= 0) v = __ldg((const float4*)(g_V1 + n_own * 256 + kq * 4));
        Ast[(kq * 4 + 0) * 32 + s] = v.x;
        Ast[(kq * 4 + 1) * 32 + s] = v.y;
        Ast[(kq * 4 + 2) * 32 + s] = v.z;
        Ast[(kq * 4 + 3) * 32 + s] = v.w;
    }
    __syncthreads();

    int half = blockIdx.y;
    int colg = tid & 31, sg = tid >> 5;
    int brow = tid >> 5, bcol = (tid & 31) * 4;
    const float* Bg = B + c * 256 + half * 128;
    float4 nb[4];
    u64 acc[2][4] = {};
    GEMM_MAIN();

    // dot 4 cols with suffix vector, butterfly over warp (32 colg = full half)
    float part[4];
#pragma unroll
    for (int p = 0; p < 2; p++) {
        float lo0, lo1, lo2, lo3, hi0, hi1, hi2, hi3;
        UNPACK64(lo0, hi0, acc[p][0]); UNPACK64(lo1, hi1, acc[p][1]);
        UNPACK64(lo2, hi2, acc[p][2]); UNPACK64(lo3, hi3, acc[p][3]);
        int l0 = base + sg * 4 + 2 * p, l1 = l0 + 1;
        int nn0 = (l0 < cnt) ? g_b4[c * NS + l0] : -1;
        int nn1 = (l1 < cnt) ? g_b4[c * NS + l1] : -1;
        int q0 = (nn0 >= 0) ? g_q[nn0] : 0;
        int q1 = (nn1 >= 0) ? g_q[nn1] : 0;
        float4 s0 = *(const float4*)(g_S + q0 * 256 + half * 128 + colg * 4);
        float4 s1 = *(const float4*)(g_S + q1 * 256 + half * 128 + colg * 4);
        part[2 * p]     = lo0 * s0.x + lo1 * s0.y + lo2 * s0.z + lo3 * s0.w;
        part[2 * p + 1] = hi0 * s1.x + hi1 * s1.y + hi2 * s1.z + hi3 * s1.w;
    }
#pragma unroll
    for (int i = 0; i < 4; i++) {
#pragma unroll
        for (int off = 16; off > 0; off >>= 1)
            part[i] += __shfl_xor_sync(0xffffffffu, part[i], off);
    }
    if (colg == 0) {
#pragma unroll
        for (int i = 0; i < 4; i++) {
            int l = base + sg * 4 + i;
            int n = (l < cnt) ? g_b4[c * NS + l] : -1;
            if (n >= 0) g_part[half * NS + n] = part[i];
        }
    }
}

// Sum the two column-half partials -> final output.
__global__ void k_final(float* __restrict__ out) {
    int n = blockIdx.x * 256 + threadIdx.x;
    if (n < NS) out[n] = g_part[n] + g_part[NS + n];
}

// ---------------------------------------------------------------------------
extern "C" void kernel_launch(void* const* d_in, const int* in_sizes, int n_in,
                              void* d_out, int out_size) {
    const float* core0 = (const float*)d_in[0];
    const float* core1 = (const float*)d_in[1];
    const float* core2 = (const float*)d_in[2];
    const float* core3 = (const float*)d_in[3];
    const float* core4 = (const float*)d_in[4];
    const float* core5 = (const float*)d_in[5];
    const float* core6 = (const float*)d_in[6];
    const float* core7 = (const float*)d_in[7];
    const int*   coords = (const int*)d_in[8];
    float* out = (float*)d_out;

    k_zero<<<1, 32>>>();
    k_setup<<<80, 256>>>(core0, core1, core2, core5, core6, core7, coords);
    k_gemm3<<<dim3(136, 2), 256>>>(core3);
    k_gemm4<<<dim3(136, 2), 256>>>(core4);
    k_final<<<16, 256>>>(out);
}

// round 9
// speedup vs baseline: 2.4780x; 1.1143x over previous
#include <cuda_runtime.h>

#define NS 4096
typedef unsigned long long u64;

// f32x2 packed math (sm_103a): one FFMA2 = 2 fp32 FMAs
#define PACKDUP(d, x)  asm("mov.b64 %0, {%1, %1};" : "=l"(d) : "f"(x))
#define FFMA2(d, a, b) asm("fma.rn.f32x2 %0, %1, %2, %0;" : "+l"(d) : "l"(a), "l"(b))
#define UNPACK64(lo, hi, v) asm("mov.b64 {%0, %1}, %2;" : "=f"(lo), "=f"(hi) : "l"(v))

// ---- scratch (device globals: no allocation allowed) ----
__device__ float g_P[512 * 256];     // prefix table  (c0,c1,c2)
__device__ float g_S[512 * 256];     // suffix table  (c5,c6,c7)
__device__ float g_V1[NS * 256];     // intermediate after level-3 GEMM
__device__ float g_part[2 * NS];     // per-col-half partial dots (level 4)
__device__ int   g_p[NS];
__device__ int   g_q[NS];
__device__ int   g_cnt3[8];          // zero-init at load; k_final re-zeros after use
__device__ int   g_cnt4[8];
__device__ int   g_b3[8 * NS];
__device__ int   g_b4[8 * NS];

// ---------------------------------------------------------------------------
// Fused setup: blocks 0-31 prefix GEMMs, 32-63 suffix GEMMs, 64-79 decode.
__global__ void __launch_bounds__(256) k_setup(
    const float* __restrict__ c0, const float* __restrict__ c1,
    const float* __restrict__ c2, const float* __restrict__ c5,
    const float* __restrict__ c6, const float* __restrict__ c7,
    const int*   __restrict__ coords)
{
    __shared__ float sA[64 * 68];
    __shared__ float sB[64 * 68];
    int bid = blockIdx.x;
    int tid = threadIdx.x;

    if (bid < 32) {
        // ---------------- prefix: P[(ab,c)][col] = T[ab] @ core2[:,c,col] ----
        int cdig = bid >> 2, col0 = (bid & 3) * 64;
        for (int e = tid; e < 4096; e += 256) {
            int r = e >> 6, ab = e & 63;
            int a = ab >> 3, b = ab & 7;
            float acc = 0.f;
#pragma unroll
            for (int i = 0; i < 8; i++)
                acc += c0[a * 8 + i] * c1[(i * 8 + b) * 64 + r];
            sA[r * 68 + ab] = acc;
        }
        for (int e = tid; e < 4096; e += 256) {
            int r = e >> 6, cc = e & 63;
            sB[r * 68 + cc] = c2[(r * 8 + cdig) * 256 + col0 + cc];
        }
        __syncthreads();
        int ct = tid & 15, abt = tid >> 4;
        float acc[4][4] = {};
        for (int r = 0; r < 64; r++) {
            float4 tv = *(const float4*)&sA[r * 68 + abt * 4];
            float4 bv = *(const float4*)&sB[r * 68 + ct * 4];
            acc[0][0] += tv.x * bv.x; acc[0][1] += tv.x * bv.y; acc[0][2] += tv.x * bv.z; acc[0][3] += tv.x * bv.w;
            acc[1][0] += tv.y * bv.x; acc[1][1] += tv.y * bv.y; acc[1][2] += tv.y * bv.z; acc[1][3] += tv.y * bv.w;
            acc[2][0] += tv.z * bv.x; acc[2][1] += tv.z * bv.y; acc[2][2] += tv.z * bv.z; acc[2][3] += tv.z * bv.w;
            acc[3][0] += tv.w * bv.x; acc[3][1] += tv.w * bv.y; acc[3][2] += tv.w * bv.z; acc[3][3] += tv.w * bv.w;
        }
#pragma unroll
        for (int ii = 0; ii < 4; ii++) {
            int p = (abt * 4 + ii) * 8 + cdig;
            *(float4*)&g_P[p * 256 + col0 + ct * 4] =
                make_float4(acc[ii][0], acc[ii][1], acc[ii][2], acc[ii][3]);
        }
    } else if (bid < 64) {
        // ---------------- suffix: S[(a,bc)][row] = core5[row,a,:] @ U[bc] ----
        int b2 = bid - 32;
        int adig = b2 >> 2, row0 = (b2 & 3) * 64;
        for (int e = tid; e < 4096; e += 256) {
            int r = e >> 6, j = e & 63;
            sA[j * 68 + r] = c5[((row0 + r) * 8 + adig) * 64 + j];
        }
        for (int e = tid; e < 4096; e += 256) {
            int j = e >> 6, bc = e & 63;
            int b = bc >> 3, c = bc & 7;
            float acc = 0.f;
#pragma unroll
            for (int i = 0; i < 8; i++)
                acc += c6[(j * 8 + b) * 8 + i] * c7[i * 8 + c];
            sB[j * 68 + bc] = acc;
        }
        __syncthreads();
        int rt = tid & 15, bct = tid >> 4;
        float acc[4][4] = {};
        for (int j = 0; j < 64; j++) {
            float4 av = *(const float4*)&sA[j * 68 + rt * 4];
            float4 uv = *(const float4*)&sB[j * 68 + bct * 4];
            acc[0][0] += av.x * uv.x; acc[0][1] += av.x * uv.y; acc[0][2] += av.x * uv.z; acc[0][3] += av.x * uv.w;
            acc[1][0] += av.y * uv.x; acc[1][1] += av.y * uv.y; acc[1][2] += av.y * uv.z; acc[1][3] += av.y * uv.w;
            acc[2][0] += av.z * uv.x; acc[2][1] += av.z * uv.y; acc[2][2] += av.z * uv.z; acc[2][3] += av.z * uv.w;
            acc[3][0] += av.w * uv.x; acc[3][1] += av.w * uv.y; acc[3][2] += av.w * uv.z; acc[3][3] += av.w * uv.w;
        }
#pragma unroll
        for (int jj = 0; jj < 4; jj++) {
            int q = adig * 64 + bct * 4 + jj;
            *(float4*)&g_S[q * 256 + row0 + rt * 4] =
                make_float4(acc[0][jj], acc[1][jj], acc[2][jj], acc[3][jj]);
        }
    } else {
        // ---------------- decode ----------------
        int n = (bid - 64) * 256 + tid;
        if (n < NS) {
            int x = coords[3 * n], y = coords[3 * n + 1], z = coords[3 * n + 2];
            int d[8];
#pragma unroll
            for (int l = 0; l < 8; l++) {
                int sh = 7 - l;
                d[l] = 4 * ((x >> sh) & 1) + 2 * ((y >> sh) & 1) + ((z >> sh) & 1);
            }
            g_p[n] = d[0] * 64 + d[1] * 8 + d[2];
            g_q[n] = d[5] * 64 + d[6] * 8 + d[7];
            int pos3 = atomicAdd(&g_cnt3[d[3]], 1);
            g_b3[d[3] * NS + pos3] = n;
            int pos4 = atomicAdd(&g_cnt4[d[4]], 1);
            g_b4[d[4] * NS + pos4] = n;
        }
    }
}

// ---------------------------------------------------------------------------
// Pipelined FFMA2 GEMM: 32 samples x 128 cols (half = blockIdx.y), K=256.
// 128 threads: colg = tid&31 (4 cols), sg = tid>>5 (8 samples = 4 packed pairs).
// K in 8 chunks of 32 rows; chunk kc+1 streams gmem->regs during chunk kc's
// smem compute. Shared = Ast[256][32] (32KB) + Bs[32][128] (16KB) = 48KB.
// ~4 blocks/SM co-resident.

// map flat tile id -> (bucket, base); computed redundantly in all threads
__device__ __forceinline__ int2 tile_map(const int* __restrict__ cnt, int t) {
    int acc = 0, c = -1, base = 0;
#pragma unroll
    for (int i = 0; i < 8; i++) {
        int tiles = (cnt[i] + 31) >> 5;
        if (c < 0 && t < acc + tiles) { c = i; base = (t - acc) * 32; }
        acc += tiles;
    }
    return make_int2(c, base);
}

#define LDB(KC)                                                                \
    {                                                                          \
        _Pragma("unroll")                                                      \
        for (int p4 = 0; p4 < 8; p4++)                                         \
            nb[p4] = __ldg((const float4*)(Bg + ((KC) * 32 + p4 * 4 + brow) * 2048 + bcol)); \
    }
#define STB()                                                                  \
    {                                                                          \
        _Pragma("unroll")                                                      \
        for (int p4 = 0; p4 < 8; p4++)                                         \
            *(float4*)&Bs[(p4 * 4 + brow) * 128 + bcol] = nb[p4];              \
    }
#define CHUNK_COMPUTE(KC)                                                      \
    {                                                                          \
        _Pragma("unroll 8")                                                    \
        for (int kk = 0; kk < 32; kk++) {                                      \
            float4 b = *(const float4*)&Bs[kk * 128 + colg * 4];               \
            u64 bd0, bd1, bd2, bd3;                                            \
            PACKDUP(bd0, b.x); PACKDUP(bd1, b.y);                              \
            PACKDUP(bd2, b.z); PACKDUP(bd3, b.w);                              \
            const u64* ap = (const u64*)&Ast[((KC) * 32 + kk) * 32 + sg * 8];  \
            u64 a0 = ap[0], a1 = ap[1], a2 = ap[2], a3 = ap[3];                \
            FFMA2(acc[0][0], a0, bd0); FFMA2(acc[0][1], a0, bd1);              \
            FFMA2(acc[0][2], a0, bd2); FFMA2(acc[0][3], a0, bd3);              \
            FFMA2(acc[1][0], a1, bd0); FFMA2(acc[1][1], a1, bd1);              \
            FFMA2(acc[1][2], a1, bd2); FFMA2(acc[1][3], a1, bd3);              \
            FFMA2(acc[2][0], a2, bd0); FFMA2(acc[2][1], a2, bd1);              \
            FFMA2(acc[2][2], a2, bd2); FFMA2(acc[2][3], a2, bd3);              \
            FFMA2(acc[3][0], a3, bd0); FFMA2(acc[3][1], a3, bd1);              \
            FFMA2(acc[3][2], a3, bd2); FFMA2(acc[3][3], a3, bd3);              \
        }                                                                      \
    }
#define GEMM_MAIN()                                                            \
    LDB(0); STB(); __syncthreads();                                            \
    for (int kc = 0; kc < 8; kc++) {                                           \
        if (kc < 7) LDB(kc + 1);                                               \
        CHUNK_COMPUTE(kc);                                                     \
        __syncthreads();                                                       \
        if (kc < 7) { STB(); __syncthreads(); }                                \
    }

// A staging (transposed): thread owns sample s = tid&31; 16 float4 passes.
#define STAGE_A(SRC, ROWSEL)                                                   \
    {                                                                          \
        int s = tid & 31;                                                      \
        int li = base + s;                                                     \
        int rsel = -1;                                                         \
        if (li < cnt) { int nn = ROWSEL; rsel = nn; }                          \
        _Pragma("unroll")                                                      \
        for (int pass = 0; pass < 16; pass++) {                                \
            int kq = (tid >> 5) + 4 * pass;                                    \
            float4 v = make_float4(0.f, 0.f, 0.f, 0.f);                        \
            if (rsel >= 0) v = __ldg((const float4*)(SRC + rsel * 256 + kq * 4)); \
            Ast[(kq * 4 + 0) * 32 + s] = v.x;                                  \
            Ast[(kq * 4 + 1) * 32 + s] = v.y;                                  \
            Ast[(kq * 4 + 2) * 32 + s] = v.z;                                  \
            Ast[(kq * 4 + 3) * 32 + s] = v.w;                                  \
        }                                                                      \
    }

// Level-3: V1[n, half] = P[p[n],:] @ core3[:,c, half-cols]
__global__ void __launch_bounds__(128) k_gemm3(const float* __restrict__ B) {
    __shared__ float Ast[256 * 32];
    __shared__ float Bs[32 * 128];
    int tid = threadIdx.x;
    int2 cb = tile_map(g_cnt3, blockIdx.x);
    int c = cb.x;
    if (c < 0) return;
    int base = cb.y, cnt = g_cnt3[c];

    STAGE_A(g_P, g_p[g_b3[c * NS + li]]);
    __syncthreads();

    int half = blockIdx.y;
    int colg = tid & 31, sg = tid >> 5;
    int brow = tid >> 5, bcol = (tid & 31) * 4;
    const float* Bg = B + c * 256 + half * 128;
    float4 nb[8];
    u64 acc[4][4] = {};
    GEMM_MAIN();

#pragma unroll
    for (int p = 0; p < 4; p++) {
        float lo0, lo1, lo2, lo3, hi0, hi1, hi2, hi3;
        UNPACK64(lo0, hi0, acc[p][0]); UNPACK64(lo1, hi1, acc[p][1]);
        UNPACK64(lo2, hi2, acc[p][2]); UNPACK64(lo3, hi3, acc[p][3]);
        int l0 = base + sg * 8 + 2 * p, l1 = l0 + 1;
        int n0 = (l0 < cnt) ? g_b3[c * NS + l0] : -1;
        int n1 = (l1 < cnt) ? g_b3[c * NS + l1] : -1;
        if (n0 >= 0) *(float4*)&g_V1[n0 * 256 + half * 128 + colg * 4] =
            make_float4(lo0, lo1, lo2, lo3);
        if (n1 >= 0) *(float4*)&g_V1[n1 * 256 + half * 128 + colg * 4] =
            make_float4(hi0, hi1, hi2, hi3);
    }
}

// Level-4 + suffix dot: g_part[half][n] = (V1[n]@C4[c])[half] . S[q[n]][half]
__global__ void __launch_bounds__(128) k_gemm4(const float* __restrict__ B) {
    __shared__ float Ast[256 * 32];
    __shared__ float Bs[32 * 128];
    int tid = threadIdx.x;
    int2 cb = tile_map(g_cnt4, blockIdx.x);
    int c = cb.x;
    if (c < 0) return;
    int base = cb.y, cnt = g_cnt4[c];

    STAGE_A(g_V1, g_b4[c * NS + li]);
    __syncthreads();

    int half = blockIdx.y;
    int colg = tid & 31, sg = tid >> 5;
    int brow = tid >> 5, bcol = (tid & 31) * 4;
    const float* Bg = B + c * 256 + half * 128;
    float4 nb[8];
    u64 acc[4][4] = {};
    GEMM_MAIN();

    // per-sample dot with suffix vector; butterfly over warp (32 colg = half)
    float part[8];
#pragma unroll
    for (int p = 0; p < 4; p++) {
        float lo0, lo1, lo2, lo3, hi0, hi1, hi2, hi3;
        UNPACK64(lo0, hi0, acc[p][0]); UNPACK64(lo1, hi1, acc[p][1]);
        UNPACK64(lo2, hi2, acc[p][2]); UNPACK64(lo3, hi3, acc[p][3]);
        int l0 = base + sg * 8 + 2 * p, l1 = l0 + 1;
        int nn0 = (l0 < cnt) ? g_b4[c * NS + l0] : -1;
        int nn1 = (l1 < cnt) ? g_b4[c * NS + l1] : -1;
        int q0 = (nn0 >= 0) ? g_q[nn0] : 0;
        int q1 = (nn1 >= 0) ? g_q[nn1] : 0;
        float4 s0 = *(const float4*)(g_S + q0 * 256 + half * 128 + colg * 4);
        float4 s1 = *(const float4*)(g_S + q1 * 256 + half * 128 + colg * 4);
        part[2 * p]     = lo0 * s0.x + lo1 * s0.y + lo2 * s0.z + lo3 * s0.w;
        part[2 * p + 1] = hi0 * s1.x + hi1 * s1.y + hi2 * s1.z + hi3 * s1.w;
    }
#pragma unroll
    for (int i = 0; i < 8; i++) {
#pragma unroll
        for (int off = 16; off > 0; off >>= 1)
            part[i] += __shfl_xor_sync(0xffffffffu, part[i], off);
    }
    if (colg == 0) {
#pragma unroll
        for (int i = 0; i < 8; i++) {
            int l = base + sg * 8 + i;
            int n = (l < cnt) ? g_b4[c * NS + l] : -1;
            if (n >= 0) g_part[half * NS + n] = part[i];
        }
    }
}

// Sum the two column-half partials -> output; self-clean bucket counters so
// the next execution (graph replay) starts from a zeroed state.
__global__ void k_final(float* __restrict__ out) {
    int n = blockIdx.x * 256 + threadIdx.x;
    if (n < NS) out[n] = g_part[n] + g_part[NS + n];
    if (blockIdx.x == 0 && threadIdx.x < 8) {
        g_cnt3[threadIdx.x] = 0;
        g_cnt4[threadIdx.x] = 0;
    }
}

// ---------------------------------------------------------------------------
extern "C" void kernel_launch(void* const* d_in, const int* in_sizes, int n_in,
                              void* d_out, int out_size) {
    const float* core0 = (const float*)d_in[0];
    const float* core1 = (const float*)d_in[1];
    const float* core2 = (const float*)d_in[2];
    const float* core3 = (const float*)d_in[3];
    const float* core4 = (const float*)d_in[4];
    const float* core5 = (const float*)d_in[5];
    const float* core6 = (const float*)d_in[6];
    const float* core7 = (const float*)d_in[7];
    const int*   coords = (const int*)d_in[8];
    float* out = (float*)d_out;

    k_setup<<<80, 256>>>(core0, core1, core2, core5, core6, core7, coords);
    k_gemm3<<<dim3(136, 2), 128>>>(core3);
    k_gemm4<<<dim3(136, 2), 128>>>(core4);
    k_final<<<16, 256>>>(out);
}